// round 2
// baseline (speedup 1.0000x reference)
#include <cuda_runtime.h>
#include <math.h>
#include <float.h>

#define H 1024
#define F 2048
#define V 50257

// ---------------- scratch (device globals; no allocation) ----------------
__device__ float g_attn_logits[F];
__device__ float g_part[16 * H];        // attn_applied partials
__device__ float g_attn_applied[H];
__device__ float g_x[H];                // combined + relu
__device__ float g_gx[3 * H];
__device__ float g_gh[3 * H];
__device__ float g_hnew[H];             // aligned copy of new hidden state
__device__ float2 g_lsm_part[64];       // (max, sum) partials
__device__ float2 g_lsm_fin;            // (max, log(sum))

// ---------------- helpers ----------------
__device__ __forceinline__ float warp_sum(float v) {
#pragma unroll
    for (int o = 16; o; o >>= 1) v += __shfl_xor_sync(0xffffffffu, v, o);
    return v;
}

__device__ __forceinline__ float dot4(float4 a, float4 b) {
    return a.x * b.x + a.y * b.y + a.z * b.z + a.w * b.w;
}

// ---------------- 1) attn logits: row f -> dot([emb[tok]; h], attn_W[f]) + b[f]
// blockDim (32, 8), grid F/8
__global__ void k_attn_logits(const float* __restrict__ emb, const int* __restrict__ tok,
                              const float* __restrict__ hvec,
                              const float* __restrict__ W, const float* __restrict__ b) {
    int row = blockIdx.x * 8 + threadIdx.y;
    const float4* e  = (const float4*)(emb + (size_t)tok[0] * H);
    const float4* hv = (const float4*)hvec;
    const float4* w1 = (const float4*)(W + (size_t)row * (2 * H));
    const float4* w2 = w1 + H / 4;
    float acc = 0.f;
#pragma unroll
    for (int i = threadIdx.x; i < H / 4; i += 32) {
        acc += dot4(e[i],  w1[i]);
        acc += dot4(hv[i], w2[i]);
    }
    acc = warp_sum(acc);
    if (threadIdx.x == 0) g_attn_logits[row] = acc + b[row];
}

// ---------------- 2) softmax over F=2048, one block of 1024 threads
// writes attention weights (scalar stores) into the output slot AND nowhere else
__global__ void k_attn_softmax(float* __restrict__ wout) {
    __shared__ float sh[32];
    int tid = threadIdx.x;
    float a = g_attn_logits[tid];
    float b = g_attn_logits[tid + 1024];
    float m = fmaxf(a, b);
#pragma unroll
    for (int o = 16; o; o >>= 1) m = fmaxf(m, __shfl_xor_sync(0xffffffffu, m, o));
    if ((tid & 31) == 0) sh[tid >> 5] = m;
    __syncthreads();
    if (tid < 32) {
        float v = sh[tid];
#pragma unroll
        for (int o = 16; o; o >>= 1) v = fmaxf(v, __shfl_xor_sync(0xffffffffu, v, o));
        sh[tid] = v;
    }
    __syncthreads();
    m = sh[0];
    float e0 = __expf(a - m), e1 = __expf(b - m);
    float s = warp_sum(e0 + e1);
    __syncthreads();
    if ((tid & 31) == 0) sh[tid >> 5] = s;
    __syncthreads();
    if (tid < 32) {
        float v = sh[tid];
        v = warp_sum(v);
        sh[tid] = v;
    }
    __syncthreads();
    float inv = 1.f / sh[0];
    // store to scratch for downstream (aligned) and to output slot (scalar, any alignment)
    g_attn_logits[tid]        = e0 * inv;   // reuse scratch as normalized weights
    g_attn_logits[tid + 1024] = e1 * inv;
    wout[tid]        = e0 * inv;
    wout[tid + 1024] = e1 * inv;
}

// ---------------- 3a) attn_applied partials: part[p][h] = sum_{f in chunk p} w[f]*enc[f][h]
// blockDim 256, grid (H/256=4, 16); chunk = F/16 = 128
__global__ void k_attn_applied_part(const float* __restrict__ enc) {
    int hh = blockIdx.x * 256 + threadIdx.x;
    int f0 = blockIdx.y * (F / 16);
    float acc = 0.f;
#pragma unroll 4
    for (int f = f0; f < f0 + F / 16; ++f)
        acc = fmaf(g_attn_logits[f], enc[(size_t)f * H + hh], acc);
    g_part[blockIdx.y * H + hh] = acc;
}

// ---------------- 3b) reduce 16 partials; 1 block of 1024
__global__ void k_attn_applied_red() {
    int i = threadIdx.x;
    float acc = 0.f;
#pragma unroll
    for (int p = 0; p < 16; ++p) acc += g_part[p * H + i];
    g_attn_applied[i] = acc;
}

// ---------------- 4) combine: x[i] = relu(dot([emb[tok]; attn_applied], comb_W[i]) + b[i])
// blockDim (32,8), grid H/8
__global__ void k_combine(const float* __restrict__ emb, const int* __restrict__ tok,
                          const float* __restrict__ W, const float* __restrict__ b) {
    int row = blockIdx.x * 8 + threadIdx.y;
    const float4* e  = (const float4*)(emb + (size_t)tok[0] * H);
    const float4* av = (const float4*)g_attn_applied;
    const float4* w1 = (const float4*)(W + (size_t)row * (2 * H));
    const float4* w2 = w1 + H / 4;
    float acc = 0.f;
#pragma unroll
    for (int i = threadIdx.x; i < H / 4; i += 32) {
        acc += dot4(e[i],  w1[i]);
        acc += dot4(av[i], w2[i]);
    }
    acc = warp_sum(acc);
    if (threadIdx.x == 0) g_x[row] = fmaxf(acc + b[row], 0.f);
}

// ---------------- 5) GRU gemvs: rows 0..3071 -> gx = W_ih·x + b_ih ; rows 3072..6143 -> gh = W_hh·h + b_hh
// blockDim (32,8), grid 6144/8 = 768
__global__ void k_gru_gemv(const float* __restrict__ W_ih, const float* __restrict__ W_hh,
                           const float* __restrict__ b_ih, const float* __restrict__ b_hh,
                           const float* __restrict__ hvec) {
    int row = blockIdx.x * 8 + threadIdx.y;
    const float4* w;
    const float4* v;
    if (row < 3 * H) {
        w = (const float4*)(W_ih + (size_t)row * H);
        v = (const float4*)g_x;
    } else {
        w = (const float4*)(W_hh + (size_t)(row - 3 * H) * H);
        v = (const float4*)hvec;
    }
    float acc = 0.f;
#pragma unroll
    for (int i = threadIdx.x; i < H / 4; i += 32)
        acc += dot4(v[i], w[i]);
    acc = warp_sum(acc);
    if (threadIdx.x == 0) {
        if (row < 3 * H) g_gx[row] = acc + b_ih[row];
        else             g_gh[row - 3 * H] = acc + b_hh[row - 3 * H];
    }
}

// ---------------- 6) gates -> h_new; write aligned scratch + output slot (scalar)
__global__ void k_gates(const float* __restrict__ hvec, float* __restrict__ hout) {
    int i = threadIdx.x;   // 1024 threads, 1 block
    float r = 1.f / (1.f + __expf(-(g_gx[i]       + g_gh[i])));
    float z = 1.f / (1.f + __expf(-(g_gx[H + i]   + g_gh[H + i])));
    float n = tanhf(g_gx[2 * H + i] + r * g_gh[2 * H + i]);
    float hn = (1.f - z) * n + z * hvec[i];
    g_hnew[i] = hn;
    hout[i] = hn;        // scalar store: alignment-safe at any offset
}

// ---------------- 7) output logits: 50257 rows x 1024 (the dominant kernel)
// blockDim (32,8), grid ceil(V/8); reads g_hnew (aligned), scalar store to out
__global__ void k_out_logits(const float* __restrict__ W,
                             const float* __restrict__ b, float* __restrict__ out) {
    int row = blockIdx.x * 8 + threadIdx.y;
    if (row >= V) return;
    const float4* hv = (const float4*)g_hnew;
    const float4* w  = (const float4*)(W + (size_t)row * H);
    float acc = 0.f;
#pragma unroll
    for (int i = threadIdx.x; i < H / 4; i += 32)
        acc += dot4(hv[i], w[i]);
    acc = warp_sum(acc);
    if (threadIdx.x == 0) out[row] = acc + b[row];
}

// ---------------- 8a) online (max,sum) partial reduce: 64 blocks x 256
__global__ void k_lsm_part(const float* __restrict__ logits) {
    __shared__ float sm[256], ss[256];
    int tid = threadIdx.x;
    float m = -FLT_MAX, s = 0.f;
    for (int v = blockIdx.x * 256 + tid; v < V; v += 64 * 256) {
        float x = logits[v];
        float nm = fmaxf(m, x);
        s = s * __expf(m - nm) + __expf(x - nm);
        m = nm;
    }
    sm[tid] = m; ss[tid] = s;
    __syncthreads();
    for (int o = 128; o; o >>= 1) {
        if (tid < o) {
            float m2 = sm[tid + o], s2 = ss[tid + o];
            float nm = fmaxf(sm[tid], m2);
            ss[tid] = ss[tid] * __expf(sm[tid] - nm) + s2 * __expf(m2 - nm);
            sm[tid] = nm;
        }
        __syncthreads();
    }
    if (tid == 0) g_lsm_part[blockIdx.x] = make_float2(sm[0], ss[0]);
}

// ---------------- 8b) final combine: 1 block of 64
__global__ void k_lsm_fin() {
    __shared__ float sm[64], ss[64];
    int tid = threadIdx.x;
    float2 p = g_lsm_part[tid];
    sm[tid] = p.x; ss[tid] = p.y;
    __syncthreads();
    for (int o = 32; o; o >>= 1) {
        if (tid < o) {
            float m2 = sm[tid + o], s2 = ss[tid + o];
            float nm = fmaxf(sm[tid], m2);
            ss[tid] = ss[tid] * __expf(sm[tid] - nm) + s2 * __expf(m2 - nm);
            sm[tid] = nm;
        }
        __syncthreads();
    }
    if (tid == 0) g_lsm_fin = make_float2(sm[0], logf(ss[0]));
}

// ---------------- 8c) subtract in place (scalar)
__global__ void k_lsm_sub(float* __restrict__ out) {
    int v = blockIdx.x * 256 + threadIdx.x;
    if (v < V) {
        float2 f = g_lsm_fin;
        out[v] = out[v] - f.x - f.y;
    }
}

// ---------------- launcher ----------------
extern "C" void kernel_launch(void* const* d_in, const int* in_sizes, int n_in,
                              void* d_out, int out_size) {
    const int*   tok     = (const int*)  d_in[0];
    const float* hidden  = (const float*)d_in[1];
    const float* enc     = (const float*)d_in[2];
    const float* emb     = (const float*)d_in[3];
    const float* attn_W  = (const float*)d_in[4];
    const float* attn_b  = (const float*)d_in[5];
    const float* comb_W  = (const float*)d_in[6];
    const float* comb_b  = (const float*)d_in[7];
    const float* W_ih    = (const float*)d_in[8];
    const float* W_hh    = (const float*)d_in[9];
    const float* b_ih    = (const float*)d_in[10];
    const float* b_hh    = (const float*)d_in[11];
    const float* out_W   = (const float*)d_in[12];
    const float* out_b   = (const float*)d_in[13];

    float* out    = (float*)d_out;       // [0, V)        : log-softmax output
    float* h_out  = out + V;             // [V, V+H)      : new hidden (scalar access only)
    float* attn_w = out + V + H;         // [V+H, V+H+F)  : attention weights (scalar access only)

    dim3 w8(32, 8);

    k_attn_logits<<<F / 8, w8>>>(emb, tok, hidden, attn_W, attn_b);
    k_attn_softmax<<<1, 1024>>>(attn_w);
    k_attn_applied_part<<<dim3(H / 256, 16), 256>>>(enc);
    k_attn_applied_red<<<1, 1024>>>();
    k_combine<<<H / 8, w8>>>(emb, tok, comb_W, comb_b);
    k_gru_gemv<<<(6 * H) / 8, w8>>>(W_ih, W_hh, b_ih, b_hh, hidden);
    k_gates<<<1, 1024>>>(hidden, h_out);
    k_out_logits<<<(V + 7) / 8, w8>>>(out_W, out_b, out);
    k_lsm_part<<<64, 256>>>(out);
    k_lsm_fin<<<1, 64>>>();
    k_lsm_sub<<<(V + 255) / 256, 256>>>(out);
}

// round 5
// speedup vs baseline: 1.1369x; 1.1369x over previous
#include <cuda_runtime.h>
#include <math.h>
#include <float.h>

#define H 1024
#define F 2048
#define V 50257
#define NB 148          // blocks == co-resident CTAs (<= SM count, GB300 has 152)
#define TPB 1024
#define NWARP (NB * 32) // 4736 warps grid-wide

// ---------------- scratch (device globals; no allocation) ----------------
__device__ float g_attn_logits[F];
__device__ float g_attn_w[F];
__device__ float g_part[64 * H];      // 64 f-chunks x H partials
__device__ float g_attn_applied[H];
__device__ float g_x[H];
__device__ float g_gx[3 * H];
__device__ float g_gh[3 * H];
__device__ float g_hnew[H];
__device__ float2 g_lsm_part[NB];
__device__ float2 g_lsm_fin;
__device__ unsigned g_bar;            // monotonic grid barrier counter

// ---------------- helpers ----------------
__device__ __forceinline__ float warp_sum(float v) {
#pragma unroll
    for (int o = 16; o; o >>= 1) v += __shfl_xor_sync(0xffffffffu, v, o);
    return v;
}
__device__ __forceinline__ float warp_max(float v) {
#pragma unroll
    for (int o = 16; o; o >>= 1) v = fmaxf(v, __shfl_xor_sync(0xffffffffu, v, o));
    return v;
}
__device__ __forceinline__ float dot4(float4 a, float4 b) {
    return a.x * b.x + a.y * b.y + a.z * b.z + a.w * b.w;
}

// Monotonic phase barrier: safe across launches (counter always left at k*NB).
// Requires all NB CTAs co-resident: __launch_bounds__(1024,1) => <=64 regs,
// 1 CTA/SM, NB=148 <= 152 SMs => wave-1 residency guaranteed.
__device__ __forceinline__ void gsync() {
    __syncthreads();
    __threadfence();
    if (threadIdx.x == 0) {
        unsigned old = atomicAdd(&g_bar, 1);
        unsigned target = (old / NB + 1) * NB;
        while (*((volatile unsigned*)&g_bar) < target) { __nanosleep(32); }
    }
    __syncthreads();
}

__global__ void __launch_bounds__(TPB, 1)
k_fused(const int* __restrict__ tok, const float* __restrict__ hvec,
        const float* __restrict__ enc, const float* __restrict__ emb,
        const float* __restrict__ attn_W, const float* __restrict__ attn_b,
        const float* __restrict__ comb_W, const float* __restrict__ comb_b,
        const float* __restrict__ W_ih, const float* __restrict__ W_hh,
        const float* __restrict__ b_ih, const float* __restrict__ b_hh,
        const float* __restrict__ out_W, const float* __restrict__ out_b,
        float* __restrict__ out, float* __restrict__ h_out,
        float* __restrict__ attn_w_out)
{
    const int tid  = threadIdx.x;
    const int wid  = tid >> 5;
    const int lane = tid & 31;
    const int gw   = blockIdx.x * 32 + wid;

    // ===== S1: attention logits (F rows, warp per row), 16 MB =====
    {
        const float4* e  = (const float4*)(emb + (size_t)tok[0] * H);
        const float4* hv = (const float4*)hvec;
        for (int row = gw; row < F; row += NWARP) {
            const float4* w1 = (const float4*)(attn_W + (size_t)row * (2 * H));
            const float4* w2 = w1 + H / 4;
            float acc = 0.f;
#pragma unroll
            for (int i = lane; i < H / 4; i += 32)
                acc += dot4(e[i], w1[i]) + dot4(hv[i], w2[i]);
            acc = warp_sum(acc);
            if (lane == 0) g_attn_logits[row] = acc + attn_b[row];
        }
    }
    gsync();

    // ===== S2: softmax over F (block 0) =====
    if (blockIdx.x == 0) {
        __shared__ float sh[32];
        float a = g_attn_logits[tid];
        float b = g_attn_logits[tid + 1024];
        float m = warp_max(fmaxf(a, b));
        if (lane == 0) sh[wid] = m;
        __syncthreads();
        if (tid < 32) sh[tid] = warp_max(sh[tid]);
        __syncthreads();
        m = sh[0];
        float e0 = __expf(a - m), e1 = __expf(b - m);
        float s = warp_sum(e0 + e1);
        __syncthreads();
        if (lane == 0) sh[wid] = s;
        __syncthreads();
        if (tid < 32) sh[tid] = warp_sum(sh[tid]);
        __syncthreads();
        float inv = 1.f / sh[0];
        g_attn_w[tid]         = e0 * inv;
        g_attn_w[tid + 1024]  = e1 * inv;
        attn_w_out[tid]        = e0 * inv;   // scalar store, alignment-safe
        attn_w_out[tid + 1024] = e1 * inv;
    }
    gsync();

    // ===== S3a: attn_applied partials: 64 blocks x 32 f-rows each, 8 MB =====
    if (blockIdx.x < 64) {
        int f0 = blockIdx.x * 32;
        float acc = 0.f;
#pragma unroll 8
        for (int f = f0; f < f0 + 32; ++f)
            acc = fmaf(g_attn_w[f], enc[(size_t)f * H + tid], acc);
        g_part[blockIdx.x * H + tid] = acc;
    }
    gsync();

    // ===== S3b: reduce 64 partials per column (4 blocks x 256 cols) =====
    if (blockIdx.x < 4) {
        __shared__ float red[4][256];
        int c = blockIdx.x * 256 + (tid & 255);
        int g = tid >> 8;                         // 0..3 groups of 16 chunks
        float acc = 0.f;
#pragma unroll
        for (int p = g * 16; p < g * 16 + 16; ++p) acc += g_part[p * H + c];
        red[g][tid & 255] = acc;
        __syncthreads();
        if (g == 0)
            g_attn_applied[c] = red[0][tid] + red[1][tid] + red[2][tid] + red[3][tid];
    }
    gsync();

    // ===== S4: combine + relu (H rows, warp per row), 8 MB =====
    {
        const float4* e  = (const float4*)(emb + (size_t)tok[0] * H);
        const float4* av = (const float4*)g_attn_applied;
        for (int row = gw; row < H; row += NWARP) {
            const float4* w1 = (const float4*)(comb_W + (size_t)row * (2 * H));
            const float4* w2 = w1 + H / 4;
            float acc = 0.f;
#pragma unroll
            for (int i = lane; i < H / 4; i += 32)
                acc += dot4(e[i], w1[i]) + dot4(av[i], w2[i]);
            acc = warp_sum(acc);
            if (lane == 0) g_x[row] = fmaxf(acc + comb_b[row], 0.f);
        }
    }
    gsync();

    // ===== S5: GRU GEMVs (6H rows, warp per row), 24 MB =====
    {
        const float4* xv = (const float4*)g_x;
        const float4* hv = (const float4*)hvec;
        for (int row = gw; row < 6 * H; row += NWARP) {
            const float4* w;
            const float4* v;
            if (row < 3 * H) { w = (const float4*)(W_ih + (size_t)row * H);           v = xv; }
            else             { w = (const float4*)(W_hh + (size_t)(row - 3 * H) * H); v = hv; }
            float acc = 0.f;
#pragma unroll
            for (int i = lane; i < H / 4; i += 32) acc += dot4(v[i], w[i]);
            acc = warp_sum(acc);
            if (lane == 0) {
                if (row < 3 * H) g_gx[row]         = acc + b_ih[row];
                else             g_gh[row - 3 * H] = acc + b_hh[row - 3 * H];
            }
        }
    }
    gsync();

    // ===== S6: gates -> h_new (block 0) =====
    if (blockIdx.x == 0) {
        float r = 1.f / (1.f + __expf(-(g_gx[tid]     + g_gh[tid])));
        float z = 1.f / (1.f + __expf(-(g_gx[H + tid] + g_gh[H + tid])));
        float n = tanhf(g_gx[2 * H + tid] + r * g_gh[2 * H + tid]);
        float hn = (1.f - z) * n + z * hvec[tid];
        g_hnew[tid] = hn;
        h_out[tid] = hn;                       // scalar store, alignment-safe
    }
    gsync();

    // ===== S7: output logits (V rows, warp per row), 206 MB — dominant =====
    {
        __shared__ float4 sh_h[256];
        if (tid < 256) sh_h[tid] = ((const float4*)g_hnew)[tid];
        __syncthreads();
        for (int row = gw; row < V; row += NWARP) {
            const float4* w = (const float4*)(out_W + (size_t)row * H);
            float acc = 0.f;
#pragma unroll
            for (int i = lane; i < 256; i += 32) acc += dot4(sh_h[i], w[i]);
            acc = warp_sum(acc);
            if (lane == 0) out[row] = acc + out_b[row];
        }
    }
    gsync();

    // ===== S8a: per-block online (max,sum) over logits =====
    {
        __shared__ float sm[32], ss[32];
        int v = blockIdx.x * TPB + tid;        // NB*TPB > V: <=1 elem/thread
        float m = -FLT_MAX, s = 0.f;
        if (v < V) { m = out[v]; s = 1.f; }
#pragma unroll
        for (int o = 16; o; o >>= 1) {
            float m2 = __shfl_xor_sync(0xffffffffu, m, o);
            float s2 = __shfl_xor_sync(0xffffffffu, s, o);
            float nm = fmaxf(m, m2);
            s = s * __expf(m - nm) + s2 * __expf(m2 - nm);
            m = nm;
        }
        if (lane == 0) { sm[wid] = m; ss[wid] = s; }
        __syncthreads();
        if (tid < 32) {
            m = sm[tid]; s = ss[tid];
#pragma unroll
            for (int o = 16; o; o >>= 1) {
                float m2 = __shfl_xor_sync(0xffffffffu, m, o);
                float s2 = __shfl_xor_sync(0xffffffffu, s, o);
                float nm = fmaxf(m, m2);
                s = s * __expf(m - nm) + s2 * __expf(m2 - nm);
                m = nm;
            }
            if (tid == 0) g_lsm_part[blockIdx.x] = make_float2(m, s);
        }
    }
    gsync();

    // ===== S8b: combine NB partials (block 0, warp 0 only — sync-free) =====
    if (blockIdx.x == 0 && wid == 0) {
        float m = -FLT_MAX, s = 0.f;
        for (int i = lane; i < NB; i += 32) {          // fixed per-lane order
            float2 p = g_lsm_part[i];
            float nm = fmaxf(m, p.x);
            s = s * __expf(m - nm) + p.y * __expf(p.x - nm);
            m = nm;
        }
#pragma unroll
        for (int o = 16; o; o >>= 1) {
            float m2 = __shfl_xor_sync(0xffffffffu, m, o);
            float s2 = __shfl_xor_sync(0xffffffffu, s, o);
            float nm = fmaxf(m, m2);
            s = s * __expf(m - nm) + s2 * __expf(m2 - nm);
            m = nm;
        }
        if (lane == 0) g_lsm_fin = make_float2(m, logf(s));
    }
    gsync();

    // ===== S8c: subtract (same thread<->addr mapping as S8a) =====
    {
        int v = blockIdx.x * TPB + tid;
        if (v < V) {
            float2 f = g_lsm_fin;
            out[v] = out[v] - f.x - f.y;
        }
    }
}

// ---------------- launcher ----------------
extern "C" void kernel_launch(void* const* d_in, const int* in_sizes, int n_in,
                              void* d_out, int out_size) {
    const int*   tok     = (const int*)  d_in[0];
    const float* hidden  = (const float*)d_in[1];
    const float* enc     = (const float*)d_in[2];
    const float* emb     = (const float*)d_in[3];
    const float* attn_W  = (const float*)d_in[4];
    const float* attn_b  = (const float*)d_in[5];
    const float* comb_W  = (const float*)d_in[6];
    const float* comb_b  = (const float*)d_in[7];
    const float* W_ih    = (const float*)d_in[8];
    const float* W_hh    = (const float*)d_in[9];
    const float* b_ih    = (const float*)d_in[10];
    const float* b_hh    = (const float*)d_in[11];
    const float* out_W   = (const float*)d_in[12];
    const float* out_b   = (const float*)d_in[13];

    float* out    = (float*)d_out;       // [0, V)       log-softmax
    float* h_out  = out + V;             // [V, V+H)     new hidden (scalar stores)
    float* attn_w = out + V + H;         // [V+H, V+H+F) attention weights (scalar stores)

    k_fused<<<NB, TPB>>>(tok, hidden, enc, emb, attn_W, attn_b, comb_W, comb_b,
                         W_ih, W_hh, b_ih, b_hh, out_W, out_b,
                         out, h_out, attn_w);
}

// round 10
// speedup vs baseline: 1.3550x; 1.1918x over previous
#include <cuda_runtime.h>
#include <math.h>
#include <float.h>

#define H 1024
#define F 2048
#define V 50257
#define NB 148              // all CTAs co-resident: 1 CTA/SM, 148 <= 152 SMs
#define TPB 512             // 16 warps -> 128 regs/thread budget
#define NWARP (NB * 16)     // 2368 warps grid-wide
#define NPAIR ((V + 1) / 2) // 25129 row-pairs in the big GEMV

// ---------------- scratch (device globals; no allocation) ----------------
__device__ float g_attn_logits[F];
__device__ float g_attn_w[F];
__device__ float g_part[NB * H];     // per-block attn partials
__device__ float g_attn_applied[H];
__device__ float g_x[H];
__device__ float g_gx[3 * H];
__device__ float g_gh[3 * H];
__device__ float g_hnew[H];
__device__ float2 g_lsm_part[NB];
__device__ float2 g_lsm_fin;
__device__ unsigned g_bar;           // monotonic grid barrier counter

// ---------------- helpers ----------------
__device__ __forceinline__ float warp_sum(float v) {
#pragma unroll
    for (int o = 16; o; o >>= 1) v += __shfl_xor_sync(0xffffffffu, v, o);
    return v;
}
__device__ __forceinline__ float warp_max(float v) {
#pragma unroll
    for (int o = 16; o; o >>= 1) v = fmaxf(v, __shfl_xor_sync(0xffffffffu, v, o));
    return v;
}
__device__ __forceinline__ float dot4(float4 a, float4 b) {
    return a.x * b.x + a.y * b.y + a.z * b.z + a.w * b.w;
}

// H-wide dot: 8 front-batched LDG.128 on the weight stream (MLP 8),
// vector operand v is L1/L2-hot.
__device__ __forceinline__ float dot_H(const float4* __restrict__ w,
                                       const float4* __restrict__ v, int lane) {
    float4 r[8];
#pragma unroll
    for (int k = 0; k < 8; ++k) r[k] = w[lane + 32 * k];
    float acc = 0.f;
#pragma unroll
    for (int k = 0; k < 8; ++k) acc += dot4(r[k], v[lane + 32 * k]);
    return acc;
}

// Monotonic phase barrier: counter always left at k*NB => graph-replay safe.
// Spin is BOUNDED: never triggers in normal operation (all 148 CTAs are
// co-resident); if residency were ever violated, we terminate instead of
// hanging the device (test fails cleanly, container survives).
__device__ __forceinline__ void gsync() {
    __syncthreads();
    __threadfence();
    if (threadIdx.x == 0) {
        unsigned old = atomicAdd(&g_bar, 1);
        unsigned target = (old / NB + 1) * NB;
        long long guard = 0;
        while (*((volatile unsigned*)&g_bar) < target) {
            __nanosleep(32);
            if (++guard > 100000000LL) break;   // ~seconds; never hit normally
        }
    }
    __syncthreads();
}

__global__ void __launch_bounds__(TPB, 1)
k_fused(const int* __restrict__ tok, const float* __restrict__ hvec,
        const float* __restrict__ enc, const float* __restrict__ emb,
        const float* __restrict__ attn_W, const float* __restrict__ attn_b,
        const float* __restrict__ comb_W, const float* __restrict__ comb_b,
        const float* __restrict__ W_ih, const float* __restrict__ W_hh,
        const float* __restrict__ b_ih, const float* __restrict__ b_hh,
        const float* __restrict__ out_W, const float* __restrict__ out_b,
        float* __restrict__ out, float* __restrict__ h_out,
        float* __restrict__ attn_w_out)
{
    const int tid  = threadIdx.x;
    const int wid  = tid >> 5;          // 0..15
    const int lane = tid & 31;
    const int gw   = blockIdx.x * 16 + wid;

    const float4* e  = (const float4*)(emb + (size_t)tok[0] * H);
    const float4* hv = (const float4*)hvec;

    // ===== A: attn logits (F rows) + gh = W_hh*h + b_hh (3H rows), 28 MB =====
    for (int r = gw; r < F + 3 * H; r += NWARP) {
        if (r < F) {
            const float4* w1 = (const float4*)(attn_W + (size_t)r * (2 * H));
            float acc = dot_H(w1, e, lane) + dot_H(w1 + H / 4, hv, lane);
            acc = warp_sum(acc);
            if (lane == 0) g_attn_logits[r] = acc + attn_b[r];
        } else {
            int row = r - F;
            const float4* w = (const float4*)(W_hh + (size_t)row * H);
            float acc = warp_sum(dot_H(w, hv, lane));
            if (lane == 0) g_gh[row] = acc + b_hh[row];
        }
    }
    gsync();

    // ===== B: softmax over F (block 0, 512 threads x 4 elems) =====
    if (blockIdx.x == 0) {
        __shared__ float sh[16];
        float x0 = g_attn_logits[tid],        x1 = g_attn_logits[tid + 512];
        float x2 = g_attn_logits[tid + 1024], x3 = g_attn_logits[tid + 1536];
        float m = fmaxf(fmaxf(x0, x1), fmaxf(x2, x3));
        m = warp_max(m);
        if (lane == 0) sh[wid] = m;
        __syncthreads();
        if (tid < 32) {
            float v = (tid < 16) ? sh[tid] : -FLT_MAX;
            v = warp_max(v);
            if (tid == 0) sh[0] = v;
        }
        __syncthreads();
        m = sh[0];
        __syncthreads();
        float e0 = __expf(x0 - m), e1 = __expf(x1 - m);
        float e2 = __expf(x2 - m), e3 = __expf(x3 - m);
        float s = warp_sum(e0 + e1 + e2 + e3);
        if (lane == 0) sh[wid] = s;
        __syncthreads();
        if (tid < 32) {
            float v = (tid < 16) ? sh[tid] : 0.f;
            v = warp_sum(v);
            if (tid == 0) sh[0] = v;
        }
        __syncthreads();
        float inv = 1.f / sh[0];
        g_attn_w[tid]        = e0 * inv;  attn_w_out[tid]        = e0 * inv;
        g_attn_w[tid + 512]  = e1 * inv;  attn_w_out[tid + 512]  = e1 * inv;
        g_attn_w[tid + 1024] = e2 * inv;  attn_w_out[tid + 1024] = e2 * inv;
        g_attn_w[tid + 1536] = e3 * inv;  attn_w_out[tid + 1536] = e3 * inv;
    }
    gsync();

    // ===== C: attn_applied partials — each block covers 14 f-rows, 8 MB =====
    {
        int f0 = blockIdx.x * 14;
        int nf = F - f0; if (nf > 14) nf = 14; if (nf < 0) nf = 0;
        float acc0 = 0.f, acc1 = 0.f;
        for (int j = 0; j < nf; ++j) {
            float wv = g_attn_w[f0 + j];
            acc0 = fmaf(wv, enc[(size_t)(f0 + j) * H + tid],       acc0);
            acc1 = fmaf(wv, enc[(size_t)(f0 + j) * H + tid + 512], acc1);
        }
        g_part[blockIdx.x * H + tid]       = acc0;
        g_part[blockIdx.x * H + tid + 512] = acc1;
    }
    gsync();

    // ===== D: reduce NB partials (blocks 0-1, one col/thread) =====
    if (blockIdx.x < 2) {
        int c = blockIdx.x * 512 + tid;
        float acc = 0.f;
        for (int p = 0; p < NB; ++p) acc += g_part[p * H + c];
        g_attn_applied[c] = acc;
    }
    gsync();

    // ===== E: combine + relu (H rows), 8 MB =====
    {
        const float4* av = (const float4*)g_attn_applied;
        for (int r = gw; r < H; r += NWARP) {
            const float4* w1 = (const float4*)(comb_W + (size_t)r * (2 * H));
            float acc = dot_H(w1, e, lane) + dot_H(w1 + H / 4, av, lane);
            acc = warp_sum(acc);
            if (lane == 0) g_x[r] = fmaxf(acc + comb_b[r], 0.f);
        }
    }
    gsync();

    // ===== F: gx = W_ih*x + b_ih (3H rows), 12 MB =====
    {
        const float4* xv = (const float4*)g_x;
        for (int r = gw; r < 3 * H; r += NWARP) {
            const float4* w = (const float4*)(W_ih + (size_t)r * H);
            float acc = warp_sum(dot_H(w, xv, lane));
            if (lane == 0) g_gx[r] = acc + b_ih[r];
        }
    }
    gsync();

    // ===== G: gates -> h_new (block 0, 2 elems/thread) =====
    if (blockIdx.x == 0) {
#pragma unroll
        for (int k = 0; k < 2; ++k) {
            int i = tid + k * 512;
            float r = 1.f / (1.f + __expf(-(g_gx[i]     + g_gh[i])));
            float z = 1.f / (1.f + __expf(-(g_gx[H + i] + g_gh[H + i])));
            float n = tanhf(g_gx[2 * H + i] + r * g_gh[2 * H + i]);
            float hn = (1.f - z) * n + z * hvec[i];
            g_hnew[i] = hn;
            h_out[i] = hn;                     // scalar store, alignment-safe
        }
    }
    gsync();

    // ===== H: output logits (V rows, 2 rows/warp-iter, reg-resident h), 206 MB
    //          + fused per-block online (max,sum) for log-softmax =====
    {
        // preload h into registers: 8 float4/lane, fixed for whole phase
        float4 hreg[8];
        {
            const float4* hp = (const float4*)g_hnew;
#pragma unroll
            for (int k = 0; k < 8; ++k) hreg[k] = hp[lane + 32 * k];
        }
        float m = -FLT_MAX, s = 0.f;           // identical across lanes
        for (int p = gw; p < NPAIR; p += NWARP) {
            int r0 = 2 * p;
            int r1 = r0 + 1;
            bool has1 = (r1 < V);
            const float4* w0 = (const float4*)(out_W + (size_t)r0 * H);
            const float4* w1 = (const float4*)(out_W + (size_t)(has1 ? r1 : r0) * H);
            float b0 = out_b[r0];
            float b1 = out_b[has1 ? r1 : r0];
            float acc0 = 0.f, acc1 = 0.f;
#pragma unroll
            for (int half = 0; half < 2; ++half) {
                int base = lane + half * 128;  // 4 float4 per half
                float4 a[4], b[4];
#pragma unroll
                for (int k = 0; k < 4; ++k) a[k] = w0[base + 32 * k];
#pragma unroll
                for (int k = 0; k < 4; ++k) b[k] = w1[base + 32 * k];
#pragma unroll
                for (int k = 0; k < 4; ++k) {
                    acc0 += dot4(a[k], hreg[half * 4 + k]);
                    acc1 += dot4(b[k], hreg[half * 4 + k]);
                }
            }
            acc0 = warp_sum(acc0);
            acc1 = warp_sum(acc1);
            float l0 = acc0 + b0;
            if (lane == 0) out[r0] = l0;
            { float nm = fmaxf(m, l0); s = s * __expf(m - nm) + __expf(l0 - nm); m = nm; }
            if (has1) {
                float l1 = acc1 + b1;
                if (lane == 0) out[r1] = l1;
                float nm = fmaxf(m, l1); s = s * __expf(m - nm) + __expf(l1 - nm); m = nm;
            }
        }
        // block-level combine of 16 per-warp (m,s)
        __shared__ float sma[16], ssa[16];
        if (lane == 0) { sma[wid] = m; ssa[wid] = s; }
        __syncthreads();
        if (tid < 32) {
            float mm = (tid < 16) ? sma[tid] : -FLT_MAX;
            float ss = (tid < 16) ? ssa[tid] : 0.f;
#pragma unroll
            for (int o = 16; o; o >>= 1) {
                float m2 = __shfl_xor_sync(0xffffffffu, mm, o);
                float s2 = __shfl_xor_sync(0xffffffffu, ss, o);
                float nm = fmaxf(mm, m2);
                ss = ss * __expf(mm - nm) + s2 * __expf(m2 - nm);
                mm = nm;
            }
            if (tid == 0) g_lsm_part[blockIdx.x] = make_float2(mm, ss);
        }
    }
    gsync();

    // ===== I: combine NB partials (block 0, warp 0 only — sync-free) =====
    if (blockIdx.x == 0 && wid == 0) {
        float m = -FLT_MAX, s = 0.f;
        for (int i = lane; i < NB; i += 32) {      // fixed per-lane order
            float2 p = g_lsm_part[i];
            float nm = fmaxf(m, p.x);
            s = s * __expf(m - nm) + p.y * __expf(p.x - nm);
            m = nm;
        }
#pragma unroll
        for (int o = 16; o; o >>= 1) {
            float m2 = __shfl_xor_sync(0xffffffffu, m, o);
            float s2 = __shfl_xor_sync(0xffffffffu, s, o);
            float nm = fmaxf(m, m2);
            s = s * __expf(m - nm) + s2 * __expf(m2 - nm);
            m = nm;
        }
        if (lane == 0) g_lsm_fin = make_float2(m, logf(s));
    }
    gsync();

    // ===== J: subtract (one elem/thread; NB*TPB = 75776 >= V) =====
    {
        int v = blockIdx.x * TPB + tid;
        if (v < V) {
            float2 f = g_lsm_fin;
            out[v] = out[v] - f.x - f.y;
        }
    }
}

// ---------------- launcher ----------------
extern "C" void kernel_launch(void* const* d_in, const int* in_sizes, int n_in,
                              void* d_out, int out_size) {
    const int*   tok     = (const int*)  d_in[0];
    const float* hidden  = (const float*)d_in[1];
    const float* enc     = (const float*)d_in[2];
    const float* emb     = (const float*)d_in[3];
    const float* attn_W  = (const float*)d_in[4];
    const float* attn_b  = (const float*)d_in[5];
    const float* comb_W  = (const float*)d_in[6];
    const float* comb_b  = (const float*)d_in[7];
    const float* W_ih    = (const float*)d_in[8];
    const float* W_hh    = (const float*)d_in[9];
    const float* b_ih    = (const float*)d_in[10];
    const float* b_hh    = (const float*)d_in[11];
    const float* out_W   = (const float*)d_in[12];
    const float* out_b   = (const float*)d_in[13];

    float* out    = (float*)d_out;       // [0, V)       log-softmax
    float* h_out  = out + V;             // [V, V+H)     new hidden (scalar stores)
    float* attn_w = out + V + H;         // [V+H, V+H+F) attention weights (scalar stores)

    k_fused<<<NB, TPB>>>(tok, hidden, enc, emb, attn_W, attn_b, comb_W, comb_b,
                         W_ih, W_hh, b_ih, b_hh, out_W, out_b,
                         out, h_out, attn_w);
}